// round 15
// baseline (speedup 1.0000x reference)
#include <cuda_runtime.h>
#include <cuda_fp16.h>
#include <math.h>
#include <stdint.h>

#define HH 192
#define WW 448
#define HWSZ (HH*WW)
#define BB 4

// ---------------- scratch (__device__ globals; no allocation) ----------------
__device__ __half g_x[BB*HWSZ*144];
__device__ __half g_a[BB*HWSZ*128];   // ping
__device__ __half g_b[BB*HWSZ*128];   // pong
__device__ float  g_d1[BB*HWSZ*32];   // dist after 5x1 conv (NHWC fp32, ch 0..24 valid)
__device__ float  g_fpart[64];        // flow mean partials [bc][chunk]
#define WP_TOTAL 460800
__device__ __align__(16) __half g_wp[WP_TOTAL];
__device__ __align__(16) __half g_wpf[64*128];       // feat 1x1 weights [ci][co]
__device__ __align__(16) __half g_wpd[5*2*16*32];    // dist1 weights [ky][kc][krow][co32]
__device__ __align__(16) float  g_wpd2[160*32];      // dist2 weights tf32 [k=kw*32+ci][co32]

__device__ __forceinline__ float lrelu(float v){ return v >= 0.f ? v : 0.1f*v; }

__device__ __forceinline__ uint32_t smem_u32(const void* p){
    uint32_t a;
    asm("{ .reg .u64 t; cvta.to.shared.u64 t, %1; cvt.u32.u64 %0, t; }" : "=r"(a) : "l"(p));
    return a;
}
__device__ __forceinline__ void cp16(uint32_t dst, const void* src, int srcsz){
    asm volatile("cp.async.ca.shared.global [%0], [%1], 16, %2;"
        :: "r"(dst), "l"(src), "r"(srcsz) : "memory");
}
#define CP_COMMIT() asm volatile("cp.async.commit_group;" ::: "memory")
#define CP_WAIT0()  asm volatile("cp.async.wait_group 0;"  ::: "memory")

__device__ __forceinline__ void ldsm_x4(uint32_t* r, uint32_t a){
    asm volatile("ldmatrix.sync.aligned.m8n8.x4.shared.b16 {%0,%1,%2,%3}, [%4];"
        : "=r"(r[0]),"=r"(r[1]),"=r"(r[2]),"=r"(r[3]) : "r"(a));
}
__device__ __forceinline__ void ldsm_x4t(uint32_t* r, uint32_t a){
    asm volatile("ldmatrix.sync.aligned.m8n8.x4.trans.shared.b16 {%0,%1,%2,%3}, [%4];"
        : "=r"(r[0]),"=r"(r[1]),"=r"(r[2]),"=r"(r[3]) : "r"(a));
}
__device__ __forceinline__ void mma16816(float* c, const uint32_t* a, const uint32_t* b){
    asm volatile("mma.sync.aligned.m16n8k16.row.col.f32.f16.f16.f32 "
        "{%0,%1,%2,%3}, {%4,%5,%6,%7}, {%8,%9}, {%0,%1,%2,%3};"
        : "+f"(c[0]),"+f"(c[1]),"+f"(c[2]),"+f"(c[3])
        : "r"(a[0]),"r"(a[1]),"r"(a[2]),"r"(a[3]), "r"(b[0]),"r"(b[1]));
}
// fp16-accumulate variant: D/C are 2 b32 regs (4 halves)
__device__ __forceinline__ void mma16816_h(uint32_t* c, const uint32_t* a, const uint32_t* b){
    asm volatile("mma.sync.aligned.m16n8k16.row.col.f16.f16.f16.f16 "
        "{%0,%1}, {%2,%3,%4,%5}, {%6,%7}, {%0,%1};"
        : "+r"(c[0]),"+r"(c[1])
        : "r"(a[0]),"r"(a[1]),"r"(a[2]),"r"(a[3]), "r"(b[0]),"r"(b[1]));
}
__device__ __forceinline__ void mma_tf32(float* c, const uint32_t* a, const uint32_t* b){
    asm volatile("mma.sync.aligned.m16n8k8.row.col.f32.tf32.tf32.f32 "
        "{%0,%1,%2,%3}, {%4,%5,%6,%7}, {%8,%9}, {%0,%1,%2,%3};"
        : "+f"(c[0]),"+f"(c[1]),"+f"(c[2]),"+f"(c[3])
        : "r"(a[0]),"r"(a[1]),"r"(a[2]),"r"(a[3]), "r"(b[0]),"r"(b[1]));
}
__device__ __forceinline__ float to_tf32(float v){
    uint32_t r;
    asm("cvt.rna.tf32.f32 %0, %1;" : "=r"(r) : "f"(v));
    return __uint_as_float(r);
}
// fast exp on fma pipe: exp(x) for x <= 0; rel err ~1.5e-5
__device__ __forceinline__ float fexp(float x){
    float t = x * 1.4426950408889634f;
    float fi = floorf(t);
    float f = t - fi;
    float p = 1.3333558146e-3f;
    p = fmaf(p, f, 9.6181291076e-3f);
    p = fmaf(p, f, 5.5504108664e-2f);
    p = fmaf(p, f, 2.4022650696e-1f);
    p = fmaf(p, f, 6.9314718056e-1f);
    p = fmaf(p, f, 1.0f);
    int e = (int)fi;
    if (e < -126) e = -126;
    float s = __int_as_float((uint32_t)(e + 127) << 23);
    return p * s;
}

// ---------------- fused weight prep + flow-mean partials ----------------
__device__ __forceinline__ void prep_conv_one(const float* w, int idx,
        int BN, int Cin, int KC, int base, int permL1){
    int co = idx % BN; int r = idx / BN;
    int krow = r % 16; r /= 16;
    int kx = r % 3; r /= 3;
    int kc = r % KC; int ky = r / KC;
    int ci = kc*16 + krow;
    int tap = ky*3 + kx;
    float v = 0.f;
    if (ci < Cin){
        int srcci = permL1 ? (ci < 128 ? ci + 3 : ci - 128) : ci;
        v = w[(co*Cin + srcci)*9 + tap];
    }
    g_wp[base + (((ky*KC + kc)*3 + kx)*16 + krow)*BN + co] = __float2half(v);
}

#define PREP_TOTAL (165888+147456+73728+36864+18432+9216+8192+5120+5120)
#define PREP_BLOCKS ((PREP_TOTAL + 255)/256)

__global__ void prep_all(const float* __restrict__ mw1, const float* __restrict__ mw2,
                         const float* __restrict__ mw3, const float* __restrict__ mw4,
                         const float* __restrict__ mw5, const float* __restrict__ mw6,
                         const float* __restrict__ fw,  const float* __restrict__ dw1,
                         const float* __restrict__ dw2, const float* __restrict__ flow){
    __shared__ float red[256];
    if (blockIdx.x >= PREP_BLOCKS){
        int fb = blockIdx.x - PREP_BLOCKS;
        int bc = fb >> 3, chunk = fb & 7;
        const float* p = flow + bc*HWSZ + chunk*(HWSZ/8);
        float s = 0.f;
        for (int i = threadIdx.x; i < HWSZ/8; i += 256) s += p[i];
        red[threadIdx.x] = s; __syncthreads();
        for (int o = 128; o > 0; o >>= 1){
            if (threadIdx.x < o) red[threadIdx.x] += red[threadIdx.x+o];
            __syncthreads();
        }
        if (threadIdx.x == 0) g_fpart[fb] = red[0] / (float)HWSZ;
        return;
    }
    int idx = blockIdx.x*256 + threadIdx.x;
    if (idx < 165888){ prep_conv_one(mw1, idx, 128, 131, 9, 0, 1); return; }
    idx -= 165888;
    if (idx < 147456){ prep_conv_one(mw2, idx, 128, 128, 8, 165888, 0); return; }
    idx -= 147456;
    if (idx < 73728){ prep_conv_one(mw3, idx, 64, 128, 8, 313344, 0); return; }
    idx -= 73728;
    if (idx < 36864){ prep_conv_one(mw4, idx, 64, 64, 4, 387072, 0); return; }
    idx -= 36864;
    if (idx < 18432){ prep_conv_one(mw5, idx, 32, 64, 4, 423936, 0); return; }
    idx -= 18432;
    if (idx < 9216){ prep_conv_one(mw6, idx, 32, 32, 2, 442368, 0); return; }
    idx -= 9216;
    if (idx < 64*128){
        int ci = idx >> 7, co = idx & 127;
        g_wpf[ci*128 + co] = __float2half(fw[co*64 + ci]);
        return;
    }
    idx -= 64*128;
    if (idx < 5*2*16*32){
        int co = idx & 31; int r = idx >> 5;
        int krow = r % 16; r /= 16;
        int kc = r & 1; int ky = r >> 1;
        int ci = kc*16 + krow;
        float v = (co < 25) ? dw1[(co*32 + ci)*5 + ky] : 0.f;
        g_wpd[idx] = __float2half(v);
        return;
    }
    idx -= 5*2*16*32;
    if (idx < 160*32){
        int co = idx & 31; int k = idx >> 5;
        int kw = k >> 5, ci = k & 31;
        float v = (ci < 25 && co < 25) ? dw2[(co*25 + ci)*5 + kw] : 0.f;
        g_wpd2[idx] = to_tf32(v);
    }
}

// ---------------- backwarp diff + centered flow -> g_x ch 128..143 ----------------
__global__ void assemble_kernel(const float* __restrict__ t1,
                                const float* __restrict__ t2,
                                const float* __restrict__ flow){
    int idx = blockIdx.x*256 + threadIdx.x;
    if (idx >= BB*HWSZ) return;
    int b = idx / HWSZ, p = idx % HWSZ;
    int h = p / WW, w = p % WW;
    float mean0 = 0.f, mean1 = 0.f;
    #pragma unroll
    for (int i = 0; i < 8; i++){
        mean0 += g_fpart[(b*2+0)*8 + i];
        mean1 += g_fpart[(b*2+1)*8 + i];
    }
    float f0 = flow[(b*2+0)*HWSZ + p];
    float f1 = flow[(b*2+1)*HWSZ + p];
    float x = (float)w + f0*5.0f;
    float y = (float)h + f1*5.0f;
    float x0f = floorf(x), y0f = floorf(y);
    int x0 = (int)x0f, y0 = (int)y0f;
    float wx1 = x - x0f, wy1 = y - y0f;
    float wx0 = 1.f - wx1, wy0 = 1.f - wy1;
    float d2 = 0.f;
    #pragma unroll
    for (int c = 0; c < 3; c++){
        const float* img = t2 + (b*3+c)*HWSZ;
        float v00 = (y0   >= 0 && y0   < HH && x0   >= 0 && x0   < WW) ? img[y0*WW + x0]       : 0.f;
        float v01 = (y0   >= 0 && y0   < HH && x0+1 >= 0 && x0+1 < WW) ? img[y0*WW + x0+1]     : 0.f;
        float v10 = (y0+1 >= 0 && y0+1 < HH && x0   >= 0 && x0   < WW) ? img[(y0+1)*WW + x0]   : 0.f;
        float v11 = (y0+1 >= 0 && y0+1 < HH && x0+1 >= 0 && x0+1 < WW) ? img[(y0+1)*WW + x0+1] : 0.f;
        float warp = v00*(wy0*wx0) + v01*(wy0*wx1) + v10*(wy1*wx0) + v11*(wy1*wx1);
        float dv = t1[(b*3+c)*HWSZ + p] - warp;
        d2 += dv*dv;
    }
    __half hv[16];
    hv[0] = __float2half(sqrtf(d2));
    hv[1] = __float2half(f0 - mean0);
    hv[2] = __float2half(f1 - mean1);
    #pragma unroll
    for (int i = 3; i < 16; i++) hv[i] = __float2half(0.f);
    uint4* dst = reinterpret_cast<uint4*>(g_x + ((size_t)idx)*144 + 128);
    const uint4* srcv = reinterpret_cast<const uint4*>(hv);
    dst[0] = srcv[0]; dst[1] = srcv[1];
}

// ---------------- feat: 1x1 conv 64->128 via mma ----------------
__global__ void __launch_bounds__(256) feat_mma(const float* __restrict__ fin,
                                                const float* __restrict__ fb){
    __shared__ __align__(16) __half sA[64*72];
    __shared__ __align__(16) __half sB[64*136];

    int tid = threadIdx.x, wid = tid >> 5, lane = tid & 31;
    int b = blockIdx.z, y = blockIdx.y;
    int x0 = blockIdx.x * 64;
    int warp_m = wid & 3, warp_n = wid >> 2;
    int m_off = warp_m * 16, n_off = warp_n * 64;

    uint32_t sAu = smem_u32(sA), sBu = smem_u32(sB);
    int a_krow = (lane & 7) + ((lane >> 4) << 3);
    int a_mcol = m_off + (((lane >> 3) & 1) << 3);
    uint32_t aBase = sAu + (uint32_t)((a_krow*72 + a_mcol) * 2);
    uint32_t bBase = sBu + (uint32_t)(((lane & 15)*136 + n_off) * 2) + ((lane >> 4) << 4);

    float acc[8][4];
    #pragma unroll
    for (int nt = 0; nt < 8; nt++)
        #pragma unroll
        for (int r = 0; r < 4; r++) acc[nt][r] = 0.f;

    const float* fbase = fin + (size_t)b*64*HWSZ + (size_t)y*WW + x0;

    #pragma unroll
    for (int k = 0; k < 4; k++){
        int c = tid + k*256;
        int row = c >> 4, q = c & 15;
        float4 v = *reinterpret_cast<const float4*>(fbase + (size_t)row*HWSZ + q*4);
        __half2 h0 = __floats2half2_rn(v.x, v.y);
        __half2 h1 = __floats2half2_rn(v.z, v.w);
        uint32_t dst = sAu + (uint32_t)((row*72 + q*4) * 2);
        asm volatile("st.shared.v2.b32 [%0], {%1, %2};"
            :: "r"(dst), "r"(*(uint32_t*)&h0), "r"(*(uint32_t*)&h1) : "memory");
    }
    #pragma unroll
    for (int k = 0; k < 4; k++){
        int c = tid + k*256;
        int r = c >> 4, cu = c & 15;
        *reinterpret_cast<uint4*>(sB + r*136 + cu*8) =
            *reinterpret_cast<const uint4*>(g_wpf + r*128 + cu*8);
    }
    __syncthreads();

    #pragma unroll
    for (int kci = 0; kci < 4; kci++){
        uint32_t afr[4];
        ldsm_x4t(afr, aBase + (uint32_t)(kci*16*72*2));
        uint32_t bfr[8][2];
        #pragma unroll
        for (int np = 0; np < 4; np++){
            uint32_t r4[4];
            ldsm_x4t(r4, bBase + (uint32_t)(kci*16*136*2 + np*16*2));
            bfr[2*np][0] = r4[0]; bfr[2*np][1] = r4[1];
            bfr[2*np+1][0] = r4[2]; bfr[2*np+1][1] = r4[3];
        }
        #pragma unroll
        for (int nt = 0; nt < 8; nt++)
            mma16816(acc[nt], afr, bfr[nt]);
    }

    int row = lane >> 2, col = (lane & 3)*2;
    __half* obase = g_x + ((size_t)(b*HH + y)*WW + x0)*144;
    int m0 = m_off + row;
    #pragma unroll
    for (int nt = 0; nt < 8; nt++){
        int n0 = n_off + nt*8 + col;
        float bv0 = fb[n0], bv1 = fb[n0+1];
        __half2 v0 = __halves2half2(__float2half(lrelu(acc[nt][0] + bv0)),
                                    __float2half(lrelu(acc[nt][1] + bv1)));
        __half2 v1 = __halves2half2(__float2half(lrelu(acc[nt][2] + bv0)),
                                    __float2half(lrelu(acc[nt][3] + bv1)));
        *reinterpret_cast<__half2*>(obase + (size_t)m0*144 + n0)     = v0;
        *reinterpret_cast<__half2*>(obase + (size_t)(m0+8)*144 + n0) = v1;
    }
}

// ---------------- unified NHWC conv, fp16-accum experiment ----------------
// block 224 px x 32 co, 224 thr, 7 warps (32px x 32co each).
// fp16 accumulation within one (ky,kc) iteration (K<=48), promoted to fp32 per iter.
template<int BNW, int BNO>
__global__ void __launch_bounds__(224, 2) conv3x3_u(
        const __half* __restrict__ act, int CX, int KC, int cosplit,
        const float* __restrict__ bias, __half* __restrict__ out, int wp_base){
    constexpr int BNB = 32;
    constexpr int NT  = 4;              // n8 tiles per warp
    constexpr int SBS = BNB + 8;
    constexpr int ABUF = 226*48;
    constexpr int BBUF = 48*SBS*2;
    __shared__ __align__(16) __half sA[2*226*24];
    __shared__ __align__(16) __half sB[2*48*SBS];

    int tid = threadIdx.x, wid = tid >> 5, lane = tid & 31;
    int z = blockIdx.z;
    int b = z / cosplit, cog = z % cosplit;
    int n_base = cog * BNB;
    int y = blockIdx.y;
    int x0 = blockIdx.x * 224;
    int m_off = wid * 32;

    uint32_t sAu = smem_u32(sA), sBu = smem_u32(sB);

    int gylist[3]; int nky = 0;
    #pragma unroll
    for (int ky = 0; ky < 3; ky++){
        int gy = y + ky - 1;
        if (gy >= 0 && gy < HH){ gylist[nky] = (ky << 16) | gy; nky++; }
    }
    int N = nky * KC;

    float acc[2][NT][4];
    #pragma unroll
    for (int mt = 0; mt < 2; mt++)
        #pragma unroll
        for (int nt = 0; nt < NT; nt++)
            #pragma unroll
            for (int r = 0; r < 4; r++) acc[mt][nt][r] = 0.f;

    const size_t brow = (size_t)b * HH;

    auto stage = [&](int it){
        int buf = it & 1;
        int kykey = gylist[it / KC];
        int ky = kykey >> 16, gy = kykey & 0xffff;
        int kc = it % KC;
        const __half* arowb = act + ((brow + gy)*WW)*CX + kc*16;
        uint32_t adst = sAu + buf*ABUF;
        for (int c = tid; c < 452; c += 224){
            int r = c >> 1, hf = c & 1;
            int gx = x0 - 1 + r;
            int ok = (gx >= 0 && gx < WW) ? 16 : 0;
            int gxc = gx < 0 ? 0 : (gx >= WW ? WW-1 : gx);
            cp16(adst + r*48 + hf*16, arowb + (size_t)gxc*CX + hf*8, ok);
        }
        const __half* wsrc = g_wp + wp_base + (size_t)((ky*KC + kc)*48) * BNW + n_base;
        uint32_t bdst = sBu + buf*BBUF;
        constexpr int CPR = BNB/8;
        for (int c = tid; c < 48*CPR; c += 224){
            int r = c / CPR, cu = c % CPR;
            cp16(bdst + (r*SBS + cu*8)*2, wsrc + (size_t)r*BNW + cu*8, 16);
        }
        CP_COMMIT();
    };

    stage(0);
    for (int it = 0; it < N; it++){
        CP_WAIT0();
        __syncthreads();
        if (it + 1 < N) stage(it+1);
        int buf = it & 1;
        uint32_t aBase = sAu + buf*ABUF + ((lane & 15)*48) + ((lane >> 4)*16);
        uint32_t bBase = sBu + buf*BBUF + ((lane & 15)*SBS)*2 + ((lane >> 4)*16);
        // fp16 partial accumulators for this iteration
        uint32_t facc[2][NT][2];
        #pragma unroll
        for (int mt = 0; mt < 2; mt++)
            #pragma unroll
            for (int nt = 0; nt < NT; nt++){ facc[mt][nt][0] = 0u; facc[mt][nt][1] = 0u; }
        #pragma unroll
        for (int kx = 0; kx < 3; kx++){
            uint32_t afr[2][4];
            ldsm_x4(afr[0], aBase + (m_off + kx)*48);
            ldsm_x4(afr[1], aBase + (m_off + kx + 16)*48);
            uint32_t bfr[NT][2];
            #pragma unroll
            for (int np = 0; np < NT/2; np++){
                uint32_t r4[4];
                ldsm_x4t(r4, bBase + (kx*16)*SBS*2 + np*16*2);
                bfr[2*np][0] = r4[0]; bfr[2*np][1] = r4[1];
                bfr[2*np+1][0] = r4[2]; bfr[2*np+1][1] = r4[3];
            }
            #pragma unroll
            for (int mt = 0; mt < 2; mt++)
                #pragma unroll
                for (int nt = 0; nt < NT; nt++)
                    mma16816_h(facc[mt][nt], afr[mt], bfr[nt]);
        }
        // promote to fp32 shadow
        #pragma unroll
        for (int mt = 0; mt < 2; mt++)
            #pragma unroll
            for (int nt = 0; nt < NT; nt++){
                float2 f0 = __half22float2(*reinterpret_cast<__half2*>(&facc[mt][nt][0]));
                float2 f1 = __half22float2(*reinterpret_cast<__half2*>(&facc[mt][nt][1]));
                acc[mt][nt][0] += f0.x; acc[mt][nt][1] += f0.y;
                acc[mt][nt][2] += f1.x; acc[mt][nt][3] += f1.y;
            }
    }

    int row = lane >> 2, col = (lane & 3)*2;
    __half* obase = out + ((brow + y)*WW + x0) * BNO + n_base;
    #pragma unroll
    for (int mt = 0; mt < 2; mt++){
        int m0 = m_off + mt*16 + row;
        #pragma unroll
        for (int nt = 0; nt < NT; nt++){
            int n0 = nt*8 + col;
            float bv0 = bias[n_base + n0], bv1 = bias[n_base + n0 + 1];
            __half2 v0 = __halves2half2(__float2half(lrelu(acc[mt][nt][0] + bv0)),
                                        __float2half(lrelu(acc[mt][nt][1] + bv1)));
            __half2 v1 = __halves2half2(__float2half(lrelu(acc[mt][nt][2] + bv0)),
                                        __float2half(lrelu(acc[mt][nt][3] + bv1)));
            *reinterpret_cast<__half2*>(obase + (size_t)m0*BNO + n0)       = v0;
            *reinterpret_cast<__half2*>(obase + (size_t)(m0+8)*BNO + n0)   = v1;
        }
    }
}

// ---------------- dist1: 5x1 conv 32->25(pad32) via mma -> g_d1 NHWC fp32 ----------------
__global__ void __launch_bounds__(448) dist1_mma(const __half* __restrict__ act,
                                                 const float* __restrict__ b1){
    constexpr int SBS = 40;
    constexpr int ABUF = 224*48;
    constexpr int BBUF = 16*SBS*2;
    __shared__ __align__(16) __half sA[2*224*24];
    __shared__ __align__(16) __half sB[2*16*SBS];

    int tid = threadIdx.x, wid = tid >> 5, lane = tid & 31;
    int b = blockIdx.z, y = blockIdx.y;
    int x0 = blockIdx.x * 224;
    int warp_m = wid % 7, warp_n = wid / 7;
    int m_off = warp_m * 32, n_off = warp_n * 16;

    uint32_t sAu = smem_u32(sA), sBu = smem_u32(sB);

    int gylist[5]; int nky = 0;
    #pragma unroll
    for (int ky = 0; ky < 5; ky++){
        int gy = y + ky - 2;
        if (gy >= 0 && gy < HH){ gylist[nky] = (ky << 16) | gy; nky++; }
    }
    int N = nky * 2;

    float acc[2][2][4];
    #pragma unroll
    for (int mt = 0; mt < 2; mt++)
        #pragma unroll
        for (int nt = 0; nt < 2; nt++)
            #pragma unroll
            for (int r = 0; r < 4; r++) acc[mt][nt][r] = 0.f;

    const size_t brow = (size_t)b * HH;

    auto stage = [&](int it){
        int buf = it & 1;
        int kykey = gylist[it >> 1];
        int ky = kykey >> 16, gy = kykey & 0xffff;
        int kc = it & 1;
        const __half* arowb = act + ((brow + gy)*WW + x0)*32 + kc*16;
        uint32_t adst = sAu + buf*ABUF;
        {
            int c = tid;
            int r = c >> 1, hf = c & 1;
            cp16(adst + r*48 + hf*16, arowb + (size_t)r*32 + hf*8, 16);
        }
        const __half* wsrc = g_wpd + ((ky*2 + kc)*16) * 32;
        uint32_t bdst = sBu + buf*BBUF;
        if (tid < 64){
            int r = tid >> 2, cu = tid & 3;
            cp16(bdst + (r*SBS + cu*8)*2, wsrc + r*32 + cu*8, 16);
        }
        CP_COMMIT();
    };

    stage(0);
    for (int it = 0; it < N; it++){
        CP_WAIT0();
        __syncthreads();
        if (it + 1 < N) stage(it+1);
        int buf = it & 1;
        uint32_t aBase = sAu + buf*ABUF + ((lane & 15)*48) + ((lane >> 4)*16);
        uint32_t bBase = sBu + buf*BBUF + ((lane & 15)*SBS + n_off)*2 + ((lane >> 4)*16);
        uint32_t afr[2][4];
        ldsm_x4(afr[0], aBase + m_off*48);
        ldsm_x4(afr[1], aBase + (m_off + 16)*48);
        uint32_t r4[4];
        ldsm_x4t(r4, bBase);
        uint32_t bfr[2][2];
        bfr[0][0] = r4[0]; bfr[0][1] = r4[1];
        bfr[1][0] = r4[2]; bfr[1][1] = r4[3];
        #pragma unroll
        for (int mt = 0; mt < 2; mt++)
            #pragma unroll
            for (int nt = 0; nt < 2; nt++)
                mma16816(acc[mt][nt], afr[mt], bfr[nt]);
    }

    int row = lane >> 2, col = (lane & 3)*2;
    float* obase = g_d1 + ((brow + y)*WW + x0) * 32;
    #pragma unroll
    for (int mt = 0; mt < 2; mt++){
        int m0 = m_off + mt*16 + row;
        #pragma unroll
        for (int nt = 0; nt < 2; nt++){
            int n0 = n_off + nt*8 + col;
            float bv0 = (n0   < 25) ? b1[n0]   : 0.f;
            float bv1 = (n0+1 < 25) ? b1[n0+1] : 0.f;
            float2 v0 = make_float2(acc[mt][nt][0] + bv0, acc[mt][nt][1] + bv1);
            float2 v1 = make_float2(acc[mt][nt][2] + bv0, acc[mt][nt][3] + bv1);
            *reinterpret_cast<float2*>(obase + (size_t)m0*32 + n0)     = v0;
            *reinterpret_cast<float2*>(obase + (size_t)(m0+8)*32 + n0) = v1;
        }
    }
}

// ---------------- final: dist2 via tf32 mma + softmax + unfold (fused) ----------------
__global__ void __launch_bounds__(224) final_mma(
        const float* __restrict__ b2, const float* __restrict__ flow,
        const float* __restrict__ sxw, const float* __restrict__ sxb,
        const float* __restrict__ syw, const float* __restrict__ syb,
        float* __restrict__ out){
    __shared__ __align__(16) float sd[6064];
    __shared__ __align__(16) float sB[160*32];

    int tid = threadIdx.x, wid = tid >> 5, lane = tid & 31;
    int b = blockIdx.z, y = blockIdx.y;
    int x0 = blockIdx.x * 224;
    int gid = lane >> 2, tig = lane & 3;

    for (int c = tid; c < 228; c += 224){
        int gx = x0 + c - 2;
        if (gx >= 0 && gx < WW){
            const float4* src = reinterpret_cast<const float4*>(
                g_d1 + ((size_t)(b*HH + y)*WW + gx)*32);
            #pragma unroll
            for (int q = 0; q < 7; q++){
                float4 v = src[q];
                int c0 = q*4;
                if (c0     < 25) sd[(c0  )*233 + c] = to_tf32(v.x);
                if (c0 + 1 < 25) sd[(c0+1)*233 + c] = to_tf32(v.y);
                if (c0 + 2 < 25) sd[(c0+2)*233 + c] = to_tf32(v.z);
                if (c0 + 3 < 25) sd[(c0+3)*233 + c] = to_tf32(v.w);
            }
        } else {
            #pragma unroll
            for (int ci = 0; ci < 25; ci++) sd[ci*233 + c] = 0.f;
        }
    }
    for (int c = tid; c < 233; c += 224) sd[25*233 + c] = 0.f;
    for (int c = tid; c < 1280; c += 224)
        *reinterpret_cast<float4*>(sB + c*4) = *reinterpret_cast<const float4*>(g_wpd2 + c*4);
    __syncthreads();

    int m0 = wid * 32;
    float acc[2][4][4];
    #pragma unroll
    for (int mt = 0; mt < 2; mt++)
        #pragma unroll
        for (int nt = 0; nt < 4; nt++)
            #pragma unroll
            for (int r = 0; r < 4; r++) acc[mt][nt][r] = 0.f;

    #pragma unroll
    for (int ch = 0; ch < 20; ch++){
        int kw = ch >> 2, ci0 = (ch & 3) * 8;
        int cia = ci0 + tig;       int ca = cia < 25 ? cia : 25;
        int cib = cia + 4;         int cb = cib < 25 ? cib : 25;
        uint32_t afr[2][4];
        #pragma unroll
        for (int mt = 0; mt < 2; mt++){
            int px = m0 + mt*16 + gid;
            afr[mt][0] = __float_as_uint(sd[ca*233 + px + kw]);
            afr[mt][1] = __float_as_uint(sd[ca*233 + px + 8 + kw]);
            afr[mt][2] = __float_as_uint(sd[cb*233 + px + kw]);
            afr[mt][3] = __float_as_uint(sd[cb*233 + px + 8 + kw]);
        }
        uint32_t bfr[4][2];
        int k0 = ch * 8;
        #pragma unroll
        for (int nt = 0; nt < 4; nt++){
            bfr[nt][0] = __float_as_uint(sB[(k0 + tig    )*32 + nt*8 + gid]);
            bfr[nt][1] = __float_as_uint(sB[(k0 + tig + 4)*32 + nt*8 + gid]);
        }
        #pragma unroll
        for (int mt = 0; mt < 2; mt++)
            #pragma unroll
            for (int nt = 0; nt < 4; nt++)
                mma_tf32(acc[mt][nt], afr[mt], bfr[nt]);
    }
    __syncthreads();

    float* sdo = sd;
    #pragma unroll
    for (int mt = 0; mt < 2; mt++){
        int px = m0 + mt*16 + gid;
        #pragma unroll
        for (int nt = 0; nt < 4; nt++){
            int co = nt*8 + 2*tig;
            if (co < 25){
                sdo[px*26 + co]       = acc[mt][nt][0];
                sdo[(px+8)*26 + co]   = acc[mt][nt][2];
            }
            if (co + 1 < 25){
                sdo[px*26 + co + 1]     = acc[mt][nt][1];
                sdo[(px+8)*26 + co + 1] = acc[mt][nt][3];
            }
        }
    }
    __syncthreads();

    int px = tid, x = x0 + px;
    float v[25];
    float m = -1e30f;
    #pragma unroll
    for (int co = 0; co < 25; co++){
        float d = sdo[px*26 + co] + b2[co];
        d = -(d*d);
        v[co] = d;
        m = fmaxf(m, d);
    }
    float s = 0.f;
    #pragma unroll
    for (int co = 0; co < 25; co++){ v[co] = fexp(v[co] - m); s += v[co]; }
    float dv = __fdividef(1.f, s);

    const float* f0 = flow + (b*2+0)*HWSZ;
    const float* f1 = flow + (b*2+1)*HWSZ;
    float sx = sxb[0], sy = syb[0];
    #pragma unroll
    for (int k = 0; k < 25; k++){
        int kh = k / 5, kw = k % 5;
        int gy = y + kh - 2, gx = x + kw - 2;
        float u1 = 0.f, u2 = 0.f;
        if (gy >= 0 && gy < HH && gx >= 0 && gx < WW){
            u1 = f0[gy*WW + gx];
            u2 = f1[gy*WW + gx];
        }
        sx = fmaf(sxw[k], v[k]*u1, sx);
        sy = fmaf(syw[k], v[k]*u2, sy);
    }
    out[(b*2+0)*HWSZ + y*WW + x] = sx * dv;
    out[(b*2+1)*HWSZ + y*WW + x] = sy * dv;
}

extern "C" void kernel_launch(void* const* d_in, const int* in_sizes, int n_in,
                              void* d_out, int out_size){
    const float* t1     = (const float*)d_in[0];
    const float* t2     = (const float*)d_in[1];
    const float* ft1    = (const float*)d_in[2];
    const float* flow   = (const float*)d_in[4];
    const float* feat_w = (const float*)d_in[5];
    const float* feat_b = (const float*)d_in[6];
    const float* mw1 = (const float*)d_in[7];  const float* mb1 = (const float*)d_in[8];
    const float* mw2 = (const float*)d_in[9];  const float* mb2 = (const float*)d_in[10];
    const float* mw3 = (const float*)d_in[11]; const float* mb3 = (const float*)d_in[12];
    const float* mw4 = (const float*)d_in[13]; const float* mb4 = (const float*)d_in[14];
    const float* mw5 = (const float*)d_in[15]; const float* mb5 = (const float*)d_in[16];
    const float* mw6 = (const float*)d_in[17]; const float* mb6 = (const float*)d_in[18];
    const float* dw1 = (const float*)d_in[19]; const float* db1 = (const float*)d_in[20];
    const float* dw2 = (const float*)d_in[21]; const float* db2 = (const float*)d_in[22];
    const float* sxw = (const float*)d_in[23]; const float* sxb = (const float*)d_in[24];
    const float* syw = (const float*)d_in[25]; const float* syb = (const float*)d_in[26];
    float* out = (float*)d_out;

    __half *px = nullptr, *pa = nullptr, *pb = nullptr;
    cudaGetSymbolAddress((void**)&px, g_x);
    cudaGetSymbolAddress((void**)&pa, g_a);
    cudaGetSymbolAddress((void**)&pb, g_b);

    prep_all<<<PREP_BLOCKS + 64, 256>>>(mw1, mw2, mw3, mw4, mw5, mw6, feat_w, dw1, dw2, flow);
    assemble_kernel<<<(BB*HWSZ + 255)/256, 256>>>(t1, t2, flow);
    dim3 fgrid(7, HH, BB);
    feat_mma<<<fgrid, 256>>>(ft1, feat_b);

    // exact tiling, 32-co blocks; cosplit = Cout/32
    dim3 cg4(2, HH, BB*4);
    dim3 cg2(2, HH, BB*2);
    dim3 cg1(2, HH, BB);
    conv3x3_u<128,128><<<cg4, 224>>>(px, 144, 9, 4, mb1, pa, 0);
    conv3x3_u<128,128><<<cg4, 224>>>(pa, 128, 8, 4, mb2, pb, 165888);
    conv3x3_u< 64, 64><<<cg2, 224>>>(pb, 128, 8, 2, mb3, pa, 313344);
    conv3x3_u< 64, 64><<<cg2, 224>>>(pa,  64, 4, 2, mb4, pb, 387072);
    conv3x3_u< 32, 32><<<cg1, 224>>>(pb,  64, 4, 1, mb5, pa, 423936);
    conv3x3_u< 32, 32><<<cg1, 224>>>(pa,  32, 2, 1, mb6, pb, 442368);

    dim3 dgrid(2, HH, BB);
    dist1_mma<<<dgrid, 448>>>(pb, db1);
    final_mma<<<dgrid, 224>>>(db2, flow, sxw, sxb, syw, syb, out);
}

// round 16
// speedup vs baseline: 1.3730x; 1.3730x over previous
#include <cuda_runtime.h>
#include <cuda_fp16.h>
#include <math.h>
#include <stdint.h>

#define HH 192
#define WW 448
#define HWSZ (HH*WW)
#define BB 4

// ---------------- scratch (__device__ globals; no allocation) ----------------
__device__ __half g_x[BB*HWSZ*144];
__device__ __half g_a[BB*HWSZ*128];   // ping
__device__ __half g_b[BB*HWSZ*128];   // pong
__device__ float  g_d1[BB*HWSZ*32];   // dist after 5x1 conv (NHWC fp32, ch 0..24 valid)
__device__ float  g_fpart[64];        // flow mean partials [bc][chunk]
#define WP_TOTAL 460800
__device__ __align__(16) __half g_wp[WP_TOTAL];
__device__ __align__(16) __half g_wpf[64*128];       // feat 1x1 weights [ci][co]
__device__ __align__(16) __half g_wpd[5*2*16*32];    // dist1 weights [ky][kc][krow][co32]
__device__ __align__(16) float  g_wpd2[160*32];      // dist2 weights tf32 [k=kw*32+ci][co32]

__device__ __forceinline__ float lrelu(float v){ return v >= 0.f ? v : 0.1f*v; }

__device__ __forceinline__ uint32_t smem_u32(const void* p){
    uint32_t a;
    asm("{ .reg .u64 t; cvta.to.shared.u64 t, %1; cvt.u32.u64 %0, t; }" : "=r"(a) : "l"(p));
    return a;
}
__device__ __forceinline__ void cp16(uint32_t dst, const void* src, int srcsz){
    asm volatile("cp.async.ca.shared.global [%0], [%1], 16, %2;"
        :: "r"(dst), "l"(src), "r"(srcsz) : "memory");
}
#define CP_COMMIT() asm volatile("cp.async.commit_group;" ::: "memory")
#define CP_WAIT0()  asm volatile("cp.async.wait_group 0;"  ::: "memory")

__device__ __forceinline__ void ldsm_x4(uint32_t* r, uint32_t a){
    asm volatile("ldmatrix.sync.aligned.m8n8.x4.shared.b16 {%0,%1,%2,%3}, [%4];"
        : "=r"(r[0]),"=r"(r[1]),"=r"(r[2]),"=r"(r[3]) : "r"(a));
}
__device__ __forceinline__ void ldsm_x4t(uint32_t* r, uint32_t a){
    asm volatile("ldmatrix.sync.aligned.m8n8.x4.trans.shared.b16 {%0,%1,%2,%3}, [%4];"
        : "=r"(r[0]),"=r"(r[1]),"=r"(r[2]),"=r"(r[3]) : "r"(a));
}
__device__ __forceinline__ void mma16816(float* c, const uint32_t* a, const uint32_t* b){
    asm volatile("mma.sync.aligned.m16n8k16.row.col.f32.f16.f16.f32 "
        "{%0,%1,%2,%3}, {%4,%5,%6,%7}, {%8,%9}, {%0,%1,%2,%3};"
        : "+f"(c[0]),"+f"(c[1]),"+f"(c[2]),"+f"(c[3])
        : "r"(a[0]),"r"(a[1]),"r"(a[2]),"r"(a[3]), "r"(b[0]),"r"(b[1]));
}
__device__ __forceinline__ void mma_tf32(float* c, const uint32_t* a, const uint32_t* b){
    asm volatile("mma.sync.aligned.m16n8k8.row.col.f32.tf32.tf32.f32 "
        "{%0,%1,%2,%3}, {%4,%5,%6,%7}, {%8,%9}, {%0,%1,%2,%3};"
        : "+f"(c[0]),"+f"(c[1]),"+f"(c[2]),"+f"(c[3])
        : "r"(a[0]),"r"(a[1]),"r"(a[2]),"r"(a[3]), "r"(b[0]),"r"(b[1]));
}
__device__ __forceinline__ float to_tf32(float v){
    uint32_t r;
    asm("cvt.rna.tf32.f32 %0, %1;" : "=r"(r) : "f"(v));
    return __uint_as_float(r);
}
// fast exp on fma pipe: exp(x) for x <= 0; rel err ~1.5e-5
__device__ __forceinline__ float fexp(float x){
    float t = x * 1.4426950408889634f;
    float fi = floorf(t);
    float f = t - fi;
    float p = 1.3333558146e-3f;
    p = fmaf(p, f, 9.6181291076e-3f);
    p = fmaf(p, f, 5.5504108664e-2f);
    p = fmaf(p, f, 2.4022650696e-1f);
    p = fmaf(p, f, 6.9314718056e-1f);
    p = fmaf(p, f, 1.0f);
    int e = (int)fi;
    if (e < -126) e = -126;
    float s = __int_as_float((uint32_t)(e + 127) << 23);
    return p * s;
}

// ---------------- fused weight prep + flow-mean partials ----------------
__device__ __forceinline__ void prep_conv_one(const float* w, int idx,
        int BN, int Cin, int KC, int base, int permL1){
    int co = idx % BN; int r = idx / BN;
    int krow = r % 16; r /= 16;
    int kx = r % 3; r /= 3;
    int kc = r % KC; int ky = r / KC;
    int ci = kc*16 + krow;
    int tap = ky*3 + kx;
    float v = 0.f;
    if (ci < Cin){
        int srcci = permL1 ? (ci < 128 ? ci + 3 : ci - 128) : ci;
        v = w[(co*Cin + srcci)*9 + tap];
    }
    g_wp[base + (((ky*KC + kc)*3 + kx)*16 + krow)*BN + co] = __float2half(v);
}

#define PREP_TOTAL (165888+147456+73728+36864+18432+9216+8192+5120+5120)
#define PREP_BLOCKS ((PREP_TOTAL + 255)/256)

__global__ void prep_all(const float* __restrict__ mw1, const float* __restrict__ mw2,
                         const float* __restrict__ mw3, const float* __restrict__ mw4,
                         const float* __restrict__ mw5, const float* __restrict__ mw6,
                         const float* __restrict__ fw,  const float* __restrict__ dw1,
                         const float* __restrict__ dw2, const float* __restrict__ flow){
    __shared__ float red[256];
    if (blockIdx.x >= PREP_BLOCKS){
        int fb = blockIdx.x - PREP_BLOCKS;
        int bc = fb >> 3, chunk = fb & 7;
        const float* p = flow + bc*HWSZ + chunk*(HWSZ/8);
        float s = 0.f;
        for (int i = threadIdx.x; i < HWSZ/8; i += 256) s += p[i];
        red[threadIdx.x] = s; __syncthreads();
        for (int o = 128; o > 0; o >>= 1){
            if (threadIdx.x < o) red[threadIdx.x] += red[threadIdx.x+o];
            __syncthreads();
        }
        if (threadIdx.x == 0) g_fpart[fb] = red[0] / (float)HWSZ;
        return;
    }
    int idx = blockIdx.x*256 + threadIdx.x;
    if (idx < 165888){ prep_conv_one(mw1, idx, 128, 131, 9, 0, 1); return; }
    idx -= 165888;
    if (idx < 147456){ prep_conv_one(mw2, idx, 128, 128, 8, 165888, 0); return; }
    idx -= 147456;
    if (idx < 73728){ prep_conv_one(mw3, idx, 64, 128, 8, 313344, 0); return; }
    idx -= 73728;
    if (idx < 36864){ prep_conv_one(mw4, idx, 64, 64, 4, 387072, 0); return; }
    idx -= 36864;
    if (idx < 18432){ prep_conv_one(mw5, idx, 32, 64, 4, 423936, 0); return; }
    idx -= 18432;
    if (idx < 9216){ prep_conv_one(mw6, idx, 32, 32, 2, 442368, 0); return; }
    idx -= 9216;
    if (idx < 64*128){
        int ci = idx >> 7, co = idx & 127;
        g_wpf[ci*128 + co] = __float2half(fw[co*64 + ci]);
        return;
    }
    idx -= 64*128;
    if (idx < 5*2*16*32){
        int co = idx & 31; int r = idx >> 5;
        int krow = r % 16; r /= 16;
        int kc = r & 1; int ky = r >> 1;
        int ci = kc*16 + krow;
        float v = (co < 25) ? dw1[(co*32 + ci)*5 + ky] : 0.f;
        g_wpd[idx] = __float2half(v);
        return;
    }
    idx -= 5*2*16*32;
    if (idx < 160*32){
        int co = idx & 31; int k = idx >> 5;
        int kw = k >> 5, ci = k & 31;
        float v = (ci < 25 && co < 25) ? dw2[(co*25 + ci)*5 + kw] : 0.f;
        g_wpd2[idx] = to_tf32(v);
    }
}

// ---------------- backwarp diff + centered flow -> g_x ch 128..143 ----------------
__global__ void assemble_kernel(const float* __restrict__ t1,
                                const float* __restrict__ t2,
                                const float* __restrict__ flow){
    int idx = blockIdx.x*256 + threadIdx.x;
    if (idx >= BB*HWSZ) return;
    int b = idx / HWSZ, p = idx % HWSZ;
    int h = p / WW, w = p % WW;
    float mean0 = 0.f, mean1 = 0.f;
    #pragma unroll
    for (int i = 0; i < 8; i++){
        mean0 += g_fpart[(b*2+0)*8 + i];
        mean1 += g_fpart[(b*2+1)*8 + i];
    }
    float f0 = flow[(b*2+0)*HWSZ + p];
    float f1 = flow[(b*2+1)*HWSZ + p];
    float x = (float)w + f0*5.0f;
    float y = (float)h + f1*5.0f;
    float x0f = floorf(x), y0f = floorf(y);
    int x0 = (int)x0f, y0 = (int)y0f;
    float wx1 = x - x0f, wy1 = y - y0f;
    float wx0 = 1.f - wx1, wy0 = 1.f - wy1;
    float d2 = 0.f;
    #pragma unroll
    for (int c = 0; c < 3; c++){
        const float* img = t2 + (b*3+c)*HWSZ;
        float v00 = (y0   >= 0 && y0   < HH && x0   >= 0 && x0   < WW) ? img[y0*WW + x0]       : 0.f;
        float v01 = (y0   >= 0 && y0   < HH && x0+1 >= 0 && x0+1 < WW) ? img[y0*WW + x0+1]     : 0.f;
        float v10 = (y0+1 >= 0 && y0+1 < HH && x0   >= 0 && x0   < WW) ? img[(y0+1)*WW + x0]   : 0.f;
        float v11 = (y0+1 >= 0 && y0+1 < HH && x0+1 >= 0 && x0+1 < WW) ? img[(y0+1)*WW + x0+1] : 0.f;
        float warp = v00*(wy0*wx0) + v01*(wy0*wx1) + v10*(wy1*wx0) + v11*(wy1*wx1);
        float dv = t1[(b*3+c)*HWSZ + p] - warp;
        d2 += dv*dv;
    }
    __half hv[16];
    hv[0] = __float2half(sqrtf(d2));
    hv[1] = __float2half(f0 - mean0);
    hv[2] = __float2half(f1 - mean1);
    #pragma unroll
    for (int i = 3; i < 16; i++) hv[i] = __float2half(0.f);
    uint4* dst = reinterpret_cast<uint4*>(g_x + ((size_t)idx)*144 + 128);
    const uint4* srcv = reinterpret_cast<const uint4*>(hv);
    dst[0] = srcv[0]; dst[1] = srcv[1];
}

// ---------------- feat: 1x1 conv 64->128 via mma ----------------
__global__ void __launch_bounds__(256) feat_mma(const float* __restrict__ fin,
                                                const float* __restrict__ fb){
    __shared__ __align__(16) __half sA[64*72];
    __shared__ __align__(16) __half sB[64*136];

    int tid = threadIdx.x, wid = tid >> 5, lane = tid & 31;
    int b = blockIdx.z, y = blockIdx.y;
    int x0 = blockIdx.x * 64;
    int warp_m = wid & 3, warp_n = wid >> 2;
    int m_off = warp_m * 16, n_off = warp_n * 64;

    uint32_t sAu = smem_u32(sA), sBu = smem_u32(sB);
    int a_krow = (lane & 7) + ((lane >> 4) << 3);
    int a_mcol = m_off + (((lane >> 3) & 1) << 3);
    uint32_t aBase = sAu + (uint32_t)((a_krow*72 + a_mcol) * 2);
    uint32_t bBase = sBu + (uint32_t)(((lane & 15)*136 + n_off) * 2) + ((lane >> 4) << 4);

    float acc[8][4];
    #pragma unroll
    for (int nt = 0; nt < 8; nt++)
        #pragma unroll
        for (int r = 0; r < 4; r++) acc[nt][r] = 0.f;

    const float* fbase = fin + (size_t)b*64*HWSZ + (size_t)y*WW + x0;

    #pragma unroll
    for (int k = 0; k < 4; k++){
        int c = tid + k*256;
        int row = c >> 4, q = c & 15;
        float4 v = *reinterpret_cast<const float4*>(fbase + (size_t)row*HWSZ + q*4);
        __half2 h0 = __floats2half2_rn(v.x, v.y);
        __half2 h1 = __floats2half2_rn(v.z, v.w);
        uint32_t dst = sAu + (uint32_t)((row*72 + q*4) * 2);
        asm volatile("st.shared.v2.b32 [%0], {%1, %2};"
            :: "r"(dst), "r"(*(uint32_t*)&h0), "r"(*(uint32_t*)&h1) : "memory");
    }
    #pragma unroll
    for (int k = 0; k < 4; k++){
        int c = tid + k*256;
        int r = c >> 4, cu = c & 15;
        *reinterpret_cast<uint4*>(sB + r*136 + cu*8) =
            *reinterpret_cast<const uint4*>(g_wpf + r*128 + cu*8);
    }
    __syncthreads();

    #pragma unroll
    for (int kci = 0; kci < 4; kci++){
        uint32_t afr[4];
        ldsm_x4t(afr, aBase + (uint32_t)(kci*16*72*2));
        uint32_t bfr[8][2];
        #pragma unroll
        for (int np = 0; np < 4; np++){
            uint32_t r4[4];
            ldsm_x4t(r4, bBase + (uint32_t)(kci*16*136*2 + np*16*2));
            bfr[2*np][0] = r4[0]; bfr[2*np][1] = r4[1];
            bfr[2*np+1][0] = r4[2]; bfr[2*np+1][1] = r4[3];
        }
        #pragma unroll
        for (int nt = 0; nt < 8; nt++)
            mma16816(acc[nt], afr, bfr[nt]);
    }

    int row = lane >> 2, col = (lane & 3)*2;
    __half* obase = g_x + ((size_t)(b*HH + y)*WW + x0)*144;
    int m0 = m_off + row;
    #pragma unroll
    for (int nt = 0; nt < 8; nt++){
        int n0 = n_off + nt*8 + col;
        float bv0 = fb[n0], bv1 = fb[n0+1];
        __half2 v0 = __halves2half2(__float2half(lrelu(acc[nt][0] + bv0)),
                                    __float2half(lrelu(acc[nt][1] + bv1)));
        __half2 v1 = __halves2half2(__float2half(lrelu(acc[nt][2] + bv0)),
                                    __float2half(lrelu(acc[nt][3] + bv1)));
        *reinterpret_cast<__half2*>(obase + (size_t)m0*144 + n0)     = v0;
        *reinterpret_cast<__half2*>(obase + (size_t)(m0+8)*144 + n0) = v1;
    }
}

// ---------------- unified NHWC conv: block 224 px x BNB co, 224 thr, 7 warps 32xBNB ----------------
template<int BNB, int BNW, int BNO>
__global__ void __launch_bounds__(224, 2) conv3x3_u(
        const __half* __restrict__ act, int CX, int KC, int cosplit,
        const float* __restrict__ bias, __half* __restrict__ out, int wp_base){
    constexpr int NT  = BNB/8;
    constexpr int SBS = BNB + 8;
    constexpr int ABUF = 226*48;
    constexpr int BBUF = 48*SBS*2;
    __shared__ __align__(16) __half sA[2*226*24];
    __shared__ __align__(16) __half sB[2*48*SBS];

    int tid = threadIdx.x, wid = tid >> 5, lane = tid & 31;
    int z = blockIdx.z;
    int b = z / cosplit, cog = z % cosplit;
    int n_base = cog * BNB;
    int y = blockIdx.y;
    int x0 = blockIdx.x * 224;
    int m_off = wid * 32;

    uint32_t sAu = smem_u32(sA), sBu = smem_u32(sB);

    int gylist[3]; int nky = 0;
    #pragma unroll
    for (int ky = 0; ky < 3; ky++){
        int gy = y + ky - 1;
        if (gy >= 0 && gy < HH){ gylist[nky] = (ky << 16) | gy; nky++; }
    }
    int N = nky * KC;

    float acc[2][NT][4];
    #pragma unroll
    for (int mt = 0; mt < 2; mt++)
        #pragma unroll
        for (int nt = 0; nt < NT; nt++)
            #pragma unroll
            for (int r = 0; r < 4; r++) acc[mt][nt][r] = 0.f;

    const size_t brow = (size_t)b * HH;

    auto stage = [&](int it){
        int buf = it & 1;
        int kykey = gylist[it / KC];
        int ky = kykey >> 16, gy = kykey & 0xffff;
        int kc = it % KC;
        const __half* arowb = act + ((brow + gy)*WW)*CX + kc*16;
        uint32_t adst = sAu + buf*ABUF;
        for (int c = tid; c < 452; c += 224){
            int r = c >> 1, hf = c & 1;
            int gx = x0 - 1 + r;
            int ok = (gx >= 0 && gx < WW) ? 16 : 0;
            int gxc = gx < 0 ? 0 : (gx >= WW ? WW-1 : gx);
            cp16(adst + r*48 + hf*16, arowb + (size_t)gxc*CX + hf*8, ok);
        }
        const __half* wsrc = g_wp + wp_base + (size_t)((ky*KC + kc)*48) * BNW + n_base;
        uint32_t bdst = sBu + buf*BBUF;
        constexpr int CPR = BNB/8;
        for (int c = tid; c < 48*CPR; c += 224){
            int r = c / CPR, cu = c % CPR;
            cp16(bdst + (r*SBS + cu*8)*2, wsrc + (size_t)r*BNW + cu*8, 16);
        }
        CP_COMMIT();
    };

    stage(0);
    for (int it = 0; it < N; it++){
        CP_WAIT0();
        __syncthreads();
        if (it + 1 < N) stage(it+1);
        int buf = it & 1;
        uint32_t aBase = sAu + buf*ABUF + ((lane & 15)*48) + ((lane >> 4)*16);
        uint32_t bBase = sBu + buf*BBUF + ((lane & 15)*SBS)*2 + ((lane >> 4)*16);
        #pragma unroll
        for (int kx = 0; kx < 3; kx++){
            uint32_t afr[2][4];
            ldsm_x4(afr[0], aBase + (m_off + kx)*48);
            ldsm_x4(afr[1], aBase + (m_off + kx + 16)*48);
            uint32_t bfr[NT][2];
            #pragma unroll
            for (int np = 0; np < NT/2; np++){
                uint32_t r4[4];
                ldsm_x4t(r4, bBase + (kx*16)*SBS*2 + np*16*2);
                bfr[2*np][0] = r4[0]; bfr[2*np][1] = r4[1];
                bfr[2*np+1][0] = r4[2]; bfr[2*np+1][1] = r4[3];
            }
            #pragma unroll
            for (int mt = 0; mt < 2; mt++)
                #pragma unroll
                for (int nt = 0; nt < NT; nt++)
                    mma16816(acc[mt][nt], afr[mt], bfr[nt]);
        }
    }

    int row = lane >> 2, col = (lane & 3)*2;
    __half* obase = out + ((brow + y)*WW + x0) * BNO + n_base;
    #pragma unroll
    for (int mt = 0; mt < 2; mt++){
        int m0 = m_off + mt*16 + row;
        #pragma unroll
        for (int nt = 0; nt < NT; nt++){
            int n0 = nt*8 + col;
            float bv0 = bias[n_base + n0], bv1 = bias[n_base + n0 + 1];
            __half2 v0 = __halves2half2(__float2half(lrelu(acc[mt][nt][0] + bv0)),
                                        __float2half(lrelu(acc[mt][nt][1] + bv1)));
            __half2 v1 = __halves2half2(__float2half(lrelu(acc[mt][nt][2] + bv0)),
                                        __float2half(lrelu(acc[mt][nt][3] + bv1)));
            *reinterpret_cast<__half2*>(obase + (size_t)m0*BNO + n0)       = v0;
            *reinterpret_cast<__half2*>(obase + (size_t)(m0+8)*BNO + n0)   = v1;
        }
    }
}

// ---------------- dist1: 5x1 conv 32->25(pad32) via mma -> g_d1 NHWC fp32 ----------------
__global__ void __launch_bounds__(448) dist1_mma(const __half* __restrict__ act,
                                                 const float* __restrict__ b1){
    constexpr int SBS = 40;
    constexpr int ABUF = 224*48;
    constexpr int BBUF = 16*SBS*2;
    __shared__ __align__(16) __half sA[2*224*24];
    __shared__ __align__(16) __half sB[2*16*SBS];

    int tid = threadIdx.x, wid = tid >> 5, lane = tid & 31;
    int b = blockIdx.z, y = blockIdx.y;
    int x0 = blockIdx.x * 224;
    int warp_m = wid % 7, warp_n = wid / 7;
    int m_off = warp_m * 32, n_off = warp_n * 16;

    uint32_t sAu = smem_u32(sA), sBu = smem_u32(sB);

    int gylist[5]; int nky = 0;
    #pragma unroll
    for (int ky = 0; ky < 5; ky++){
        int gy = y + ky - 2;
        if (gy >= 0 && gy < HH){ gylist[nky] = (ky << 16) | gy; nky++; }
    }
    int N = nky * 2;

    float acc[2][2][4];
    #pragma unroll
    for (int mt = 0; mt < 2; mt++)
        #pragma unroll
        for (int nt = 0; nt < 2; nt++)
            #pragma unroll
            for (int r = 0; r < 4; r++) acc[mt][nt][r] = 0.f;

    const size_t brow = (size_t)b * HH;

    auto stage = [&](int it){
        int buf = it & 1;
        int kykey = gylist[it >> 1];
        int ky = kykey >> 16, gy = kykey & 0xffff;
        int kc = it & 1;
        const __half* arowb = act + ((brow + gy)*WW + x0)*32 + kc*16;
        uint32_t adst = sAu + buf*ABUF;
        {
            int c = tid;
            int r = c >> 1, hf = c & 1;
            cp16(adst + r*48 + hf*16, arowb + (size_t)r*32 + hf*8, 16);
        }
        const __half* wsrc = g_wpd + ((ky*2 + kc)*16) * 32;
        uint32_t bdst = sBu + buf*BBUF;
        if (tid < 64){
            int r = tid >> 2, cu = tid & 3;
            cp16(bdst + (r*SBS + cu*8)*2, wsrc + r*32 + cu*8, 16);
        }
        CP_COMMIT();
    };

    stage(0);
    for (int it = 0; it < N; it++){
        CP_WAIT0();
        __syncthreads();
        if (it + 1 < N) stage(it+1);
        int buf = it & 1;
        uint32_t aBase = sAu + buf*ABUF + ((lane & 15)*48) + ((lane >> 4)*16);
        uint32_t bBase = sBu + buf*BBUF + ((lane & 15)*SBS + n_off)*2 + ((lane >> 4)*16);
        uint32_t afr[2][4];
        ldsm_x4(afr[0], aBase + m_off*48);
        ldsm_x4(afr[1], aBase + (m_off + 16)*48);
        uint32_t r4[4];
        ldsm_x4t(r4, bBase);
        uint32_t bfr[2][2];
        bfr[0][0] = r4[0]; bfr[0][1] = r4[1];
        bfr[1][0] = r4[2]; bfr[1][1] = r4[3];
        #pragma unroll
        for (int mt = 0; mt < 2; mt++)
            #pragma unroll
            for (int nt = 0; nt < 2; nt++)
                mma16816(acc[mt][nt], afr[mt], bfr[nt]);
    }

    int row = lane >> 2, col = (lane & 3)*2;
    float* obase = g_d1 + ((brow + y)*WW + x0) * 32;
    #pragma unroll
    for (int mt = 0; mt < 2; mt++){
        int m0 = m_off + mt*16 + row;
        #pragma unroll
        for (int nt = 0; nt < 2; nt++){
            int n0 = n_off + nt*8 + col;
            float bv0 = (n0   < 25) ? b1[n0]   : 0.f;
            float bv1 = (n0+1 < 25) ? b1[n0+1] : 0.f;
            float2 v0 = make_float2(acc[mt][nt][0] + bv0, acc[mt][nt][1] + bv1);
            float2 v1 = make_float2(acc[mt][nt][2] + bv0, acc[mt][nt][3] + bv1);
            *reinterpret_cast<float2*>(obase + (size_t)m0*32 + n0)     = v0;
            *reinterpret_cast<float2*>(obase + (size_t)(m0+8)*32 + n0) = v1;
        }
    }
}

// ---------------- final: dist2 via tf32 mma + softmax + unfold (fused) ----------------
__global__ void __launch_bounds__(224) final_mma(
        const float* __restrict__ b2, const float* __restrict__ flow,
        const float* __restrict__ sxw, const float* __restrict__ sxb,
        const float* __restrict__ syw, const float* __restrict__ syb,
        float* __restrict__ out){
    __shared__ __align__(16) float sd[6064];
    __shared__ __align__(16) float sB[160*32];

    int tid = threadIdx.x, wid = tid >> 5, lane = tid & 31;
    int b = blockIdx.z, y = blockIdx.y;
    int x0 = blockIdx.x * 224;
    int gid = lane >> 2, tig = lane & 3;

    for (int c = tid; c < 228; c += 224){
        int gx = x0 + c - 2;
        if (gx >= 0 && gx < WW){
            const float4* src = reinterpret_cast<const float4*>(
                g_d1 + ((size_t)(b*HH + y)*WW + gx)*32);
            #pragma unroll
            for (int q = 0; q < 7; q++){
                float4 v = src[q];
                int c0 = q*4;
                if (c0     < 25) sd[(c0  )*233 + c] = to_tf32(v.x);
                if (c0 + 1 < 25) sd[(c0+1)*233 + c] = to_tf32(v.y);
                if (c0 + 2 < 25) sd[(c0+2)*233 + c] = to_tf32(v.z);
                if (c0 + 3 < 25) sd[(c0+3)*233 + c] = to_tf32(v.w);
            }
        } else {
            #pragma unroll
            for (int ci = 0; ci < 25; ci++) sd[ci*233 + c] = 0.f;
        }
    }
    for (int c = tid; c < 233; c += 224) sd[25*233 + c] = 0.f;
    for (int c = tid; c < 1280; c += 224)
        *reinterpret_cast<float4*>(sB + c*4) = *reinterpret_cast<const float4*>(g_wpd2 + c*4);
    __syncthreads();

    int m0 = wid * 32;
    float acc[2][4][4];
    #pragma unroll
    for (int mt = 0; mt < 2; mt++)
        #pragma unroll
        for (int nt = 0; nt < 4; nt++)
            #pragma unroll
            for (int r = 0; r < 4; r++) acc[mt][nt][r] = 0.f;

    #pragma unroll
    for (int ch = 0; ch < 20; ch++){
        int kw = ch >> 2, ci0 = (ch & 3) * 8;
        int cia = ci0 + tig;       int ca = cia < 25 ? cia : 25;
        int cib = cia + 4;         int cb = cib < 25 ? cib : 25;
        uint32_t afr[2][4];
        #pragma unroll
        for (int mt = 0; mt < 2; mt++){
            int px = m0 + mt*16 + gid;
            afr[mt][0] = __float_as_uint(sd[ca*233 + px + kw]);
            afr[mt][1] = __float_as_uint(sd[ca*233 + px + 8 + kw]);
            afr[mt][2] = __float_as_uint(sd[cb*233 + px + kw]);
            afr[mt][3] = __float_as_uint(sd[cb*233 + px + 8 + kw]);
        }
        uint32_t bfr[4][2];
        int k0 = ch * 8;
        #pragma unroll
        for (int nt = 0; nt < 4; nt++){
            bfr[nt][0] = __float_as_uint(sB[(k0 + tig    )*32 + nt*8 + gid]);
            bfr[nt][1] = __float_as_uint(sB[(k0 + tig + 4)*32 + nt*8 + gid]);
        }
        #pragma unroll
        for (int mt = 0; mt < 2; mt++)
            #pragma unroll
            for (int nt = 0; nt < 4; nt++)
                mma_tf32(acc[mt][nt], afr[mt], bfr[nt]);
    }
    __syncthreads();

    float* sdo = sd;
    #pragma unroll
    for (int mt = 0; mt < 2; mt++){
        int px = m0 + mt*16 + gid;
        #pragma unroll
        for (int nt = 0; nt < 4; nt++){
            int co = nt*8 + 2*tig;
            if (co < 25){
                sdo[px*26 + co]       = acc[mt][nt][0];
                sdo[(px+8)*26 + co]   = acc[mt][nt][2];
            }
            if (co + 1 < 25){
                sdo[px*26 + co + 1]     = acc[mt][nt][1];
                sdo[(px+8)*26 + co + 1] = acc[mt][nt][3];
            }
        }
    }
    __syncthreads();

    int px = tid, x = x0 + px;
    float v[25];
    float m = -1e30f;
    #pragma unroll
    for (int co = 0; co < 25; co++){
        float d = sdo[px*26 + co] + b2[co];
        d = -(d*d);
        v[co] = d;
        m = fmaxf(m, d);
    }
    float s = 0.f;
    #pragma unroll
    for (int co = 0; co < 25; co++){ v[co] = fexp(v[co] - m); s += v[co]; }
    float dv = __fdividef(1.f, s);

    const float* f0 = flow + (b*2+0)*HWSZ;
    const float* f1 = flow + (b*2+1)*HWSZ;
    float sx = sxb[0], sy = syb[0];
    #pragma unroll
    for (int k = 0; k < 25; k++){
        int kh = k / 5, kw = k % 5;
        int gy = y + kh - 2, gx = x + kw - 2;
        float u1 = 0.f, u2 = 0.f;
        if (gy >= 0 && gy < HH && gx >= 0 && gx < WW){
            u1 = f0[gy*WW + gx];
            u2 = f1[gy*WW + gx];
        }
        sx = fmaf(sxw[k], v[k]*u1, sx);
        sy = fmaf(syw[k], v[k]*u2, sy);
    }
    out[(b*2+0)*HWSZ + y*WW + x] = sx * dv;
    out[(b*2+1)*HWSZ + y*WW + x] = sy * dv;
}

extern "C" void kernel_launch(void* const* d_in, const int* in_sizes, int n_in,
                              void* d_out, int out_size){
    const float* t1     = (const float*)d_in[0];
    const float* t2     = (const float*)d_in[1];
    const float* ft1    = (const float*)d_in[2];
    const float* flow   = (const float*)d_in[4];
    const float* feat_w = (const float*)d_in[5];
    const float* feat_b = (const float*)d_in[6];
    const float* mw1 = (const float*)d_in[7];  const float* mb1 = (const float*)d_in[8];
    const float* mw2 = (const float*)d_in[9];  const float* mb2 = (const float*)d_in[10];
    const float* mw3 = (const float*)d_in[11]; const float* mb3 = (const float*)d_in[12];
    const float* mw4 = (const float*)d_in[13]; const float* mb4 = (const float*)d_in[14];
    const float* mw5 = (const float*)d_in[15]; const float* mb5 = (const float*)d_in[16];
    const float* mw6 = (const float*)d_in[17]; const float* mb6 = (const float*)d_in[18];
    const float* dw1 = (const float*)d_in[19]; const float* db1 = (const float*)d_in[20];
    const float* dw2 = (const float*)d_in[21]; const float* db2 = (const float*)d_in[22];
    const float* sxw = (const float*)d_in[23]; const float* sxb = (const float*)d_in[24];
    const float* syw = (const float*)d_in[25]; const float* syb = (const float*)d_in[26];
    float* out = (float*)d_out;

    __half *px = nullptr, *pa = nullptr, *pb = nullptr;
    cudaGetSymbolAddress((void**)&px, g_x);
    cudaGetSymbolAddress((void**)&pa, g_a);
    cudaGetSymbolAddress((void**)&pb, g_b);

    prep_all<<<PREP_BLOCKS + 64, 256>>>(mw1, mw2, mw3, mw4, mw5, mw6, feat_w, dw1, dw2, flow);
    assemble_kernel<<<(BB*HWSZ + 255)/256, 256>>>(t1, t2, flow);
    dim3 fgrid(7, HH, BB);
    feat_mma<<<fgrid, 256>>>(ft1, feat_b);

    dim3 cgrid2(2, HH, BB*2);
    dim3 cgrid1(2, HH, BB);
    conv3x3_u< 64,128,128><<<cgrid2, 224>>>(px, 144, 9, 2, mb1, pa, 0);
    conv3x3_u< 64,128,128><<<cgrid2, 224>>>(pa, 128, 8, 2, mb2, pb, 165888);
    conv3x3_u< 64, 64, 64><<<cgrid1, 224>>>(pb, 128, 8, 1, mb3, pa, 313344);
    conv3x3_u< 64, 64, 64><<<cgrid1, 224>>>(pa,  64, 4, 1, mb4, pb, 387072);
    conv3x3_u< 32, 32, 32><<<cgrid1, 224>>>(pb,  64, 4, 1, mb5, pa, 423936);
    conv3x3_u< 32, 32, 32><<<cgrid1, 224>>>(pa,  32, 2, 1, mb6, pb, 442368);

    dim3 dgrid(2, HH, BB);
    dist1_mma<<<dgrid, 448>>>(pb, db1);
    final_mma<<<dgrid, 224>>>(db2, flow, sxw, sxb, syw, syb, out);
}